// round 1
// baseline (speedup 1.0000x reference)
#include <cuda_runtime.h>
#include <math.h>

// ---------------- problem shape (fixed by dataset) ----------------
constexpr int B_  = 2;
constexpr int S_  = 2048;
constexpr int D_  = 1024;
constexpr int NH_ = 16;
constexpr int HD_ = 64;
constexpr int M_  = B_ * S_;   // 4096 rows

// ---------------- scratch (device globals: allocation-free) -------
__device__ float g_q[(size_t)M_ * 2 * D_];   // [4096, 2048]
__device__ float g_k[(size_t)M_ * 2 * D_];   // [4096, 2048]
__device__ float g_v[(size_t)M_ * D_];       // [4096, 1024]
__device__ float g_ctx[(size_t)M_ * D_];     // [4096, 1024]
__device__ float g_lam;

// ---------------- lambda scalar ----------------
__global__ void lam_kernel(const float* __restrict__ lq1, const float* __restrict__ lk1,
                           const float* __restrict__ lq2, const float* __restrict__ lk2) {
  int t = threadIdx.x;
  float a = lq1[t] * lk1[t] + lq1[t + 32] * lk1[t + 32];
  float b = lq2[t] * lk2[t] + lq2[t + 32] * lk2[t + 32];
  #pragma unroll
  for (int m = 16; m; m >>= 1) {
    a += __shfl_xor_sync(0xffffffffu, a, m);
    b += __shfl_xor_sync(0xffffffffu, b, m);
  }
  if (t == 0) g_lam = __expf(a) - __expf(b) + 0.8f;
}

// ---------------- 128x128x8 SGEMM with bias ----------------
// C[M,N] = A[M,K] @ B[K,N] + bias[N], all row-major fp32.
__global__ __launch_bounds__(256) void sgemm_bias(
    const float* __restrict__ A, const float* __restrict__ Bm,
    const float* __restrict__ bias, float* __restrict__ C,
    int M, int N, int K)
{
  __shared__ float As[8][128];   // As[k][row]
  __shared__ float Bs[8][128];   // Bs[k][col]

  const int bx = blockIdx.x;     // N tile
  const int by = blockIdx.y;     // M tile
  const int tid = threadIdx.x;
  const int tx = tid & 15;       // 0..15 -> 8 cols each
  const int ty = tid >> 4;       // 0..15 -> 8 rows each

  float acc[8][8];
  #pragma unroll
  for (int i = 0; i < 8; i++)
    #pragma unroll
    for (int j = 0; j < 8; j++) acc[i][j] = 0.f;

  const float* Aptr = A + (long)(by * 128) * K;
  const float* Bptr = Bm + bx * 128;

  const int a_row = tid >> 1;          // 0..127
  const int a_kk  = (tid & 1) * 4;     // 0 or 4
  const int b_kk  = tid >> 5;          // 0..7
  const int b_col = (tid & 31) * 4;    // 0..124

  for (int k0 = 0; k0 < K; k0 += 8) {
    float4 va = *(const float4*)(Aptr + (long)a_row * K + k0 + a_kk);
    As[a_kk + 0][a_row] = va.x;
    As[a_kk + 1][a_row] = va.y;
    As[a_kk + 2][a_row] = va.z;
    As[a_kk + 3][a_row] = va.w;
    float4 vb = *(const float4*)(Bptr + (long)(k0 + b_kk) * N + b_col);
    *(float4*)(&Bs[b_kk][b_col]) = vb;
    __syncthreads();

    #pragma unroll
    for (int kk = 0; kk < 8; kk++) {
      float a[8], b[8];
      *(float4*)(a)     = *(const float4*)(&As[kk][ty * 8]);
      *(float4*)(a + 4) = *(const float4*)(&As[kk][ty * 8 + 4]);
      *(float4*)(b)     = *(const float4*)(&Bs[kk][tx * 8]);
      *(float4*)(b + 4) = *(const float4*)(&Bs[kk][tx * 8 + 4]);
      #pragma unroll
      for (int i = 0; i < 8; i++)
        #pragma unroll
        for (int j = 0; j < 8; j++) acc[i][j] += a[i] * b[j];
    }
    __syncthreads();
  }

  #pragma unroll
  for (int i = 0; i < 8; i++) {
    long row = (long)(by * 128 + ty * 8 + i);
    float* cp = C + row * N + bx * 128 + tx * 8;
    const float* bp = bias + bx * 128 + tx * 8;
    #pragma unroll
    for (int j = 0; j < 8; j++) cp[j] = acc[i][j] + bp[j];
  }
}

// ---------------- fused differential flash attention ----------------
// One online-softmax step for one stream over a 64x64 tile.
// Thread map: qg = tid>>4 owns 4 query rows; cg = tid&15 owns 4 key cols
// (score phase) / 4 output dims (acc phase).
__device__ __forceinline__ void stream_step(
    const float* __restrict__ sQ, const float* __restrict__ sK,
    const float* __restrict__ sV, float* __restrict__ sP,
    const float* __restrict__ sMB,
    int qg, int cg, float m[4], float l[4], float a[4][4])
{
  float s[4][4];
  #pragma unroll
  for (int i = 0; i < 4; i++)
    #pragma unroll
    for (int j = 0; j < 4; j++) s[i][j] = 0.f;

  #pragma unroll 4
  for (int d = 0; d < 64; d++) {
    float qv[4], kv[4];
    #pragma unroll
    for (int i = 0; i < 4; i++) qv[i] = sQ[(qg * 4 + i) * 65 + d];
    #pragma unroll
    for (int j = 0; j < 4; j++) kv[j] = sK[(cg * 4 + j) * 65 + d];
    #pragma unroll
    for (int i = 0; i < 4; i++)
      #pragma unroll
      for (int j = 0; j < 4; j++) s[i][j] += qv[i] * kv[j];
  }

  float corr[4];
  #pragma unroll
  for (int i = 0; i < 4; i++) {
    #pragma unroll
    for (int j = 0; j < 4; j++) s[i][j] = s[i][j] * 0.125f + sMB[cg * 4 + j];
    float mt = fmaxf(fmaxf(s[i][0], s[i][1]), fmaxf(s[i][2], s[i][3]));
    mt = fmaxf(mt, __shfl_xor_sync(0xffffffffu, mt, 1));
    mt = fmaxf(mt, __shfl_xor_sync(0xffffffffu, mt, 2));
    mt = fmaxf(mt, __shfl_xor_sync(0xffffffffu, mt, 4));
    mt = fmaxf(mt, __shfl_xor_sync(0xffffffffu, mt, 8));
    float mn = fmaxf(m[i], mt);
    corr[i] = __expf(m[i] - mn);
    float ls = 0.f;
    #pragma unroll
    for (int j = 0; j < 4; j++) { s[i][j] = __expf(s[i][j] - mn); ls += s[i][j]; }
    ls += __shfl_xor_sync(0xffffffffu, ls, 1);
    ls += __shfl_xor_sync(0xffffffffu, ls, 2);
    ls += __shfl_xor_sync(0xffffffffu, ls, 4);
    ls += __shfl_xor_sync(0xffffffffu, ls, 8);
    l[i] = l[i] * corr[i] + ls;
    m[i] = mn;
    #pragma unroll
    for (int j = 0; j < 4; j++) sP[(qg * 4 + i) * 65 + cg * 4 + j] = s[i][j];
  }
  __syncthreads();   // P visible to all

  #pragma unroll
  for (int i = 0; i < 4; i++)
    #pragma unroll
    for (int j = 0; j < 4; j++) a[i][j] *= corr[i];

  #pragma unroll 4
  for (int k = 0; k < 64; k++) {
    float pv[4], vv[4];
    #pragma unroll
    for (int i = 0; i < 4; i++) pv[i] = sP[(qg * 4 + i) * 65 + k];
    #pragma unroll
    for (int j = 0; j < 4; j++) vv[j] = sV[k * 65 + cg * 4 + j];
    #pragma unroll
    for (int i = 0; i < 4; i++)
      #pragma unroll
      for (int j = 0; j < 4; j++) a[i][j] += pv[i] * vv[j];
  }
}

__global__ __launch_bounds__(256) void attn_kernel(const float* __restrict__ mask)
{
  extern __shared__ float sm[];
  float* sQ1 = sm;                 // 64*65
  float* sQ2 = sQ1 + 64 * 65;
  float* sK  = sQ2 + 64 * 65;
  float* sV  = sK  + 64 * 65;
  float* sP  = sV  + 64 * 65;
  float* sMB = sP  + 64 * 65;      // 64

  const int qt = blockIdx.x, h = blockIdx.y, b = blockIdx.z;
  const int tid = threadIdx.x;
  const int qg = tid >> 4;
  const int cg = tid & 15;
  const float lam = g_lam;

  const int q0 = b * S_ + qt * 64;

  for (int i = tid; i < 64 * 64; i += 256) {
    int r = i >> 6, c = i & 63;
    const float* p = g_q + (long)(q0 + r) * (2 * D_) + h * HD_ + c;
    sQ1[r * 65 + c] = p[0];
    sQ2[r * 65 + c] = p[D_];
  }

  float m1[4], l1[4], m2[4], l2[4];
  float a1[4][4], a2[4][4];
  #pragma unroll
  for (int i = 0; i < 4; i++) {
    m1[i] = m2[i] = -1e30f;
    l1[i] = l2[i] = 0.f;
    #pragma unroll
    for (int j = 0; j < 4; j++) { a1[i][j] = 0.f; a2[i][j] = 0.f; }
  }

  for (int kt = 0; kt < S_ / 64; kt++) {
    __syncthreads();   // previous tile fully consumed (also covers Q-tile load)
    const int k0 = b * S_ + kt * 64;
    for (int i = tid; i < 64 * 64; i += 256) {
      int r = i >> 6, c = i & 63;
      sK[r * 65 + c] = g_k[(long)(k0 + r) * (2 * D_) + h * HD_ + c];
      sV[r * 65 + c] = g_v[(long)(k0 + r) * D_ + h * HD_ + c];
    }
    if (tid < 64)
      sMB[tid] = (1.0f - mask[b * S_ + kt * 64 + tid]) * -10000.0f;
    __syncthreads();

    // stream 1
    stream_step(sQ1, sK, sV, sP, sMB, qg, cg, m1, l1, a1);
    __syncthreads();   // done with sK/sP

    // load K2
    for (int i = tid; i < 64 * 64; i += 256) {
      int r = i >> 6, c = i & 63;
      sK[r * 65 + c] = g_k[(long)(k0 + r) * (2 * D_) + D_ + h * HD_ + c];
    }
    __syncthreads();

    // stream 2
    stream_step(sQ2, sK, sV, sP, sMB, qg, cg, m2, l2, a2);
  }

  #pragma unroll
  for (int i = 0; i < 4; i++) {
    float inv1 = 1.0f / l1[i];
    float inv2 = lam / l2[i];
    #pragma unroll
    for (int j = 0; j < 4; j++) {
      g_ctx[(long)(q0 + qg * 4 + i) * D_ + h * HD_ + cg * 4 + j] =
          a1[i][j] * inv1 - a2[i][j] * inv2;
    }
  }
}

// ---------------- launch ----------------
extern "C" void kernel_launch(void* const* d_in, const int* in_sizes, int n_in,
                              void* d_out, int out_size) {
  const float* hs  = (const float*)d_in[0];
  const float* msk = (const float*)d_in[1];
  const float* Wq  = (const float*)d_in[2];
  const float* bq  = (const float*)d_in[3];
  const float* Wk  = (const float*)d_in[4];
  const float* bk  = (const float*)d_in[5];
  const float* Wv  = (const float*)d_in[6];
  const float* bv  = (const float*)d_in[7];
  const float* Wo  = (const float*)d_in[8];
  const float* bo  = (const float*)d_in[9];
  const float* lq1 = (const float*)d_in[10];
  const float* lk1 = (const float*)d_in[11];
  const float* lq2 = (const float*)d_in[12];
  const float* lk2 = (const float*)d_in[13];
  float* out = (float*)d_out;

  float *dq, *dk, *dv, *dctx;
  cudaGetSymbolAddress((void**)&dq,   g_q);
  cudaGetSymbolAddress((void**)&dk,   g_k);
  cudaGetSymbolAddress((void**)&dv,   g_v);
  cudaGetSymbolAddress((void**)&dctx, g_ctx);

  lam_kernel<<<1, 32>>>(lq1, lk1, lq2, lk2);

  dim3 thr(256);
  sgemm_bias<<<dim3(2 * D_ / 128, M_ / 128), thr>>>(hs, Wq, bq, dq, M_, 2 * D_, D_);
  sgemm_bias<<<dim3(2 * D_ / 128, M_ / 128), thr>>>(hs, Wk, bk, dk, M_, 2 * D_, D_);
  sgemm_bias<<<dim3(D_ / 128, M_ / 128), thr>>>(hs, Wv, bv, dv, M_, D_, D_);

  size_t smem = (size_t)(5 * 64 * 65 + 64) * sizeof(float);
  cudaFuncSetAttribute(attn_kernel, cudaFuncAttributeMaxDynamicSharedMemorySize, (int)smem);
  attn_kernel<<<dim3(S_ / 64, NH_, B_), thr, smem>>>(msk);

  sgemm_bias<<<dim3(D_ / 128, M_ / 128), thr>>>(dctx, Wo, bo, out, M_, D_, D_);
}

// round 5
// speedup vs baseline: 1.2345x; 1.2345x over previous
#include <cuda_runtime.h>
#include <math.h>
#include <stdint.h>

// ---------------- problem shape (fixed by dataset) ----------------
constexpr int B_  = 2;
constexpr int S_  = 2048;
constexpr int D_  = 1024;
constexpr int NH_ = 16;
constexpr int HD_ = 64;
constexpr int M_  = B_ * S_;   // 4096 rows

// ---------------- scratch (device globals: allocation-free) -------
__device__ float g_q[(size_t)M_ * 2 * D_];   // [4096, 2048]
__device__ float g_k[(size_t)M_ * 2 * D_];   // [4096, 2048]
__device__ float g_v[(size_t)M_ * D_];       // [4096, 1024]
__device__ float g_ctx[(size_t)M_ * D_];     // [4096, 1024] (tf32-rounded)
__device__ float g_hs[(size_t)M_ * D_];      // tf32-rounded hidden_states
__device__ float g_wt[(size_t)(2 * 2048 * 1024 + 2 * 1024 * 1024)]; // transposed+rounded weights
__device__ float g_lam;

// ---------------- helpers ----------------
__device__ __forceinline__ uint32_t smem_u32(const void* p) {
  uint32_t a;
  asm("{ .reg .u64 t; cvta.to.shared.u64 t, %1; cvt.u32.u64 %0, t; }" : "=r"(a) : "l"(p));
  return a;
}
__device__ __forceinline__ float tf32r(float x) {
  uint32_t u;
  asm("cvt.rna.tf32.f32 %0, %1;" : "=r"(u) : "f"(x));
  return __uint_as_float(u);
}
__device__ __forceinline__ void cp16(uint32_t s, const void* g) {
  asm volatile("cp.async.cg.shared.global [%0], [%1], 16;" :: "r"(s), "l"(g));
}
#define CP_COMMIT()  asm volatile("cp.async.commit_group;" ::: "memory")
#define CP_WAIT(n)   asm volatile("cp.async.wait_group %0;" :: "n"(n) : "memory")

__device__ __forceinline__ void mma_tf32(float c[4], uint32_t a0, uint32_t a1,
                                         uint32_t a2, uint32_t a3,
                                         uint32_t b0, uint32_t b1) {
  asm volatile(
      "mma.sync.aligned.m16n8k8.row.col.f32.tf32.tf32.f32 "
      "{%0,%1,%2,%3}, {%4,%5,%6,%7}, {%8,%9}, {%0,%1,%2,%3};"
      : "+f"(c[0]), "+f"(c[1]), "+f"(c[2]), "+f"(c[3])
      : "r"(a0), "r"(a1), "r"(a2), "r"(a3), "r"(b0), "r"(b1));
}

// ---------------- lambda scalar ----------------
__global__ void lam_kernel(const float* __restrict__ lq1, const float* __restrict__ lk1,
                           const float* __restrict__ lq2, const float* __restrict__ lk2) {
  int t = threadIdx.x;
  float a = lq1[t] * lk1[t] + lq1[t + 32] * lk1[t + 32];
  float b = lq2[t] * lk2[t] + lq2[t + 32] * lk2[t + 32];
  #pragma unroll
  for (int m = 16; m; m >>= 1) {
    a += __shfl_xor_sync(0xffffffffu, a, m);
    b += __shfl_xor_sync(0xffffffffu, b, m);
  }
  if (t == 0) g_lam = __expf(a) - __expf(b) + 0.8f;
}

// ---------------- tf32-round copy ----------------
__global__ __launch_bounds__(256) void round_copy(const float* __restrict__ in,
                                                  float* __restrict__ out, int n4) {
  int i = blockIdx.x * blockDim.x + threadIdx.x;
  if (i < n4) {
    float4 v = ((const float4*)in)[i];
    v.x = tf32r(v.x); v.y = tf32r(v.y); v.z = tf32r(v.z); v.w = tf32r(v.w);
    ((float4*)out)[i] = v;
  }
}

// ---------------- weight transpose + tf32 round: Wt[n][k] = W[k][n] ------
__global__ __launch_bounds__(256) void transpose_k(const float* __restrict__ W,
                                                   float* __restrict__ Wt, int K, int N) {
  __shared__ float tl[32][33];
  int n0 = blockIdx.x * 32, k0 = blockIdx.y * 32;
  int tx = threadIdx.x, ty = threadIdx.y;
  #pragma unroll
  for (int i = 0; i < 32; i += 8)
    tl[ty + i][tx] = W[(size_t)(k0 + ty + i) * N + n0 + tx];
  __syncthreads();
  #pragma unroll
  for (int i = 0; i < 32; i += 8)
    Wt[(size_t)(n0 + ty + i) * K + k0 + tx] = tf32r(tl[tx][ty + i]);
}

// ---------------- tf32 mma.sync GEMM: C[M,N] = A[M,K] @ Bt[N,K]^T + bias --
// CTA 128x128, BK=32, 4 warps of 64x64, double-buffered cp.async.
constexpr int GPAD = 36;                       // floats per smem row (128B data + pad)
constexpr int GBUF = 2 * 128 * GPAD;           // floats per stage (A+B)
constexpr int GSMEM_SZ = 2 * GBUF * 4;         // bytes, two stages

__global__ __launch_bounds__(128) void gemm_mma(
    const float* __restrict__ A, const float* __restrict__ Bt,
    const float* __restrict__ bias, float* __restrict__ C,
    int M, int N, int K)
{
  extern __shared__ float sm[];
  const uint32_t sb = smem_u32(sm);
  const int t = threadIdx.x;
  const int wid = t >> 5, lane = t & 31;
  const int g = lane >> 2, tg = lane & 3;      // mma fragment coords
  const int wm = wid >> 1, wn = wid & 1;       // 2x2 warp grid, 64x64 each
  const int m0 = blockIdx.y * 128;
  const int n0 = blockIdx.x * 128;
  const int NK = K / 32;

  float acc[4][8][4];
  #pragma unroll
  for (int mi = 0; mi < 4; mi++)
    #pragma unroll
    for (int nj = 0; nj < 8; nj++)
      #pragma unroll
      for (int c = 0; c < 4; c++) acc[mi][nj][c] = 0.f;

  // stage s: A at sm + s*GBUF, B at sm + s*GBUF + 128*GPAD. Thread t loads row t.
  auto load_tile = [&](int kt, int s) {
    const int k0 = kt * 32;
    uint32_t sa = sb + (uint32_t)(s * GBUF + t * GPAD) * 4;
    uint32_t sbf = sa + (uint32_t)(128 * GPAD) * 4;
    const float* ga = A  + (size_t)(m0 + t) * K + k0;
    const float* gb = Bt + (size_t)(n0 + t) * K + k0;
    #pragma unroll
    for (int c = 0; c < 8; c++) {
      cp16(sa  + c * 16, ga + c * 4);
      cp16(sbf + c * 16, gb + c * 4);
    }
  };

  load_tile(0, 0);
  CP_COMMIT();

  for (int kt = 0; kt < NK; kt++) {
    const int cur = kt & 1;
    if (kt + 1 < NK) { load_tile(kt + 1, cur ^ 1); CP_COMMIT(); CP_WAIT(1); }
    else             { CP_WAIT(0); }
    __syncthreads();

    const float* sA = sm + cur * GBUF;
    const float* sB = sA + 128 * GPAD;

    #pragma unroll
    for (int kk = 0; kk < 4; kk++) {
      const int k0 = kk * 8;
      uint32_t af[4][4], bf[8][2];
      #pragma unroll
      for (int mi = 0; mi < 4; mi++) {
        const float* r0 = sA + (wm * 64 + mi * 16 + g) * GPAD + k0;
        const float* r1 = r0 + 8 * GPAD;
        af[mi][0] = __float_as_uint(r0[tg]);
        af[mi][1] = __float_as_uint(r1[tg]);
        af[mi][2] = __float_as_uint(r0[tg + 4]);
        af[mi][3] = __float_as_uint(r1[tg + 4]);
      }
      #pragma unroll
      for (int nj = 0; nj < 8; nj++) {
        const float* rb = sB + (wn * 64 + nj * 8 + g) * GPAD + k0;
        bf[nj][0] = __float_as_uint(rb[tg]);
        bf[nj][1] = __float_as_uint(rb[tg + 4]);
      }
      #pragma unroll
      for (int mi = 0; mi < 4; mi++)
        #pragma unroll
        for (int nj = 0; nj < 8; nj++)
          mma_tf32(acc[mi][nj], af[mi][0], af[mi][1], af[mi][2], af[mi][3],
                   bf[nj][0], bf[nj][1]);
    }
    __syncthreads();
  }

  // epilogue
  #pragma unroll
  for (int mi = 0; mi < 4; mi++) {
    const int row0 = m0 + wm * 64 + mi * 16 + g;
    #pragma unroll
    for (int nj = 0; nj < 8; nj++) {
      const int col = n0 + wn * 64 + nj * 8 + tg * 2;
      float bx = bias[col], by = bias[col + 1];
      float2 v0 = { acc[mi][nj][0] + bx, acc[mi][nj][1] + by };
      float2 v1 = { acc[mi][nj][2] + bx, acc[mi][nj][3] + by };
      *(float2*)(C + (size_t)row0 * N + col) = v0;
      *(float2*)(C + (size_t)(row0 + 8) * N + col) = v1;
    }
  }
}

// ---------------- fused differential flash attention --------
__device__ __forceinline__ void stream_step(
    const float* __restrict__ sQ, const float* __restrict__ sK,
    const float* __restrict__ sV, float* __restrict__ sP,
    const float* __restrict__ sMB,
    int qg, int cg, float m[4], float l[4], float a[4][4])
{
  float s[4][4];
  #pragma unroll
  for (int i = 0; i < 4; i++)
    #pragma unroll
    for (int j = 0; j < 4; j++) s[i][j] = 0.f;

  #pragma unroll 4
  for (int d = 0; d < 64; d++) {
    float qv[4], kv[4];
    #pragma unroll
    for (int i = 0; i < 4; i++) qv[i] = sQ[(qg * 4 + i) * 65 + d];
    #pragma unroll
    for (int j = 0; j < 4; j++) kv[j] = sK[(cg * 4 + j) * 65 + d];
    #pragma unroll
    for (int i = 0; i < 4; i++)
      #pragma unroll
      for (int j = 0; j < 4; j++) s[i][j] += qv[i] * kv[j];
  }

  float corr[4];
  #pragma unroll
  for (int i = 0; i < 4; i++) {
    #pragma unroll
    for (int j = 0; j < 4; j++) s[i][j] = s[i][j] * 0.125f + sMB[cg * 4 + j];
    float mt = fmaxf(fmaxf(s[i][0], s[i][1]), fmaxf(s[i][2], s[i][3]));
    mt = fmaxf(mt, __shfl_xor_sync(0xffffffffu, mt, 1));
    mt = fmaxf(mt, __shfl_xor_sync(0xffffffffu, mt, 2));
    mt = fmaxf(mt, __shfl_xor_sync(0xffffffffu, mt, 4));
    mt = fmaxf(mt, __shfl_xor_sync(0xffffffffu, mt, 8));
    float mn = fmaxf(m[i], mt);
    corr[i] = __expf(m[i] - mn);
    float ls = 0.f;
    #pragma unroll
    for (int j = 0; j < 4; j++) { s[i][j] = __expf(s[i][j] - mn); ls += s[i][j]; }
    ls += __shfl_xor_sync(0xffffffffu, ls, 1);
    ls += __shfl_xor_sync(0xffffffffu, ls, 2);
    ls += __shfl_xor_sync(0xffffffffu, ls, 4);
    ls += __shfl_xor_sync(0xffffffffu, ls, 8);
    l[i] = l[i] * corr[i] + ls;
    m[i] = mn;
    #pragma unroll
    for (int j = 0; j < 4; j++) sP[(qg * 4 + i) * 65 + cg * 4 + j] = s[i][j];
  }
  __syncthreads();

  #pragma unroll
  for (int i = 0; i < 4; i++)
    #pragma unroll
    for (int j = 0; j < 4; j++) a[i][j] *= corr[i];

  #pragma unroll 4
  for (int k = 0; k < 64; k++) {
    float pv[4], vv[4];
    #pragma unroll
    for (int i = 0; i < 4; i++) pv[i] = sP[(qg * 4 + i) * 65 + k];
    #pragma unroll
    for (int j = 0; j < 4; j++) vv[j] = sV[k * 65 + cg * 4 + j];
    #pragma unroll
    for (int i = 0; i < 4; i++)
      #pragma unroll
      for (int j = 0; j < 4; j++) a[i][j] += pv[i] * vv[j];
  }
}

__global__ __launch_bounds__(256) void attn_kernel(const float* __restrict__ mask)
{
  extern __shared__ float smf[];
  float* sQ1 = smf;
  float* sQ2 = sQ1 + 64 * 65;
  float* sK  = sQ2 + 64 * 65;
  float* sV  = sK  + 64 * 65;
  float* sP  = sV  + 64 * 65;
  float* sMB = sP  + 64 * 65;

  const int qt = blockIdx.x, h = blockIdx.y, b = blockIdx.z;
  const int tid = threadIdx.x;
  const int qg = tid >> 4;
  const int cg = tid & 15;
  const float lam = g_lam;

  const int q0 = b * S_ + qt * 64;

  for (int i = tid; i < 64 * 64; i += 256) {
    int r = i >> 6, c = i & 63;
    const float* p = g_q + (long)(q0 + r) * (2 * D_) + h * HD_ + c;
    sQ1[r * 65 + c] = p[0];
    sQ2[r * 65 + c] = p[D_];
  }

  float m1[4], l1[4], m2[4], l2[4];
  float a1[4][4], a2[4][4];
  #pragma unroll
  for (int i = 0; i < 4; i++) {
    m1[i] = m2[i] = -1e30f;
    l1[i] = l2[i] = 0.f;
    #pragma unroll
    for (int j = 0; j < 4; j++) { a1[i][j] = 0.f; a2[i][j] = 0.f; }
  }

  for (int kt = 0; kt < S_ / 64; kt++) {
    __syncthreads();
    const int k0 = b * S_ + kt * 64;
    for (int i = tid; i < 64 * 64; i += 256) {
      int r = i >> 6, c = i & 63;
      sK[r * 65 + c] = g_k[(long)(k0 + r) * (2 * D_) + h * HD_ + c];
      sV[r * 65 + c] = g_v[(long)(k0 + r) * D_ + h * HD_ + c];
    }
    if (tid < 64)
      sMB[tid] = (1.0f - mask[b * S_ + kt * 64 + tid]) * -10000.0f;
    __syncthreads();

    stream_step(sQ1, sK, sV, sP, sMB, qg, cg, m1, l1, a1);
    __syncthreads();

    for (int i = tid; i < 64 * 64; i += 256) {
      int r = i >> 6, c = i & 63;
      sK[r * 65 + c] = g_k[(long)(k0 + r) * (2 * D_) + D_ + h * HD_ + c];
    }
    __syncthreads();

    stream_step(sQ2, sK, sV, sP, sMB, qg, cg, m2, l2, a2);
  }

  #pragma unroll
  for (int i = 0; i < 4; i++) {
    float inv1 = 1.0f / l1[i];
    float inv2 = lam / l2[i];
    #pragma unroll
    for (int j = 0; j < 4; j++) {
      g_ctx[(long)(q0 + qg * 4 + i) * D_ + h * HD_ + cg * 4 + j] =
          tf32r(a1[i][j] * inv1 - a2[i][j] * inv2);
    }
  }
}

// ---------------- launch ----------------
extern "C" void kernel_launch(void* const* d_in, const int* in_sizes, int n_in,
                              void* d_out, int out_size) {
  const float* hs  = (const float*)d_in[0];
  const float* msk = (const float*)d_in[1];
  const float* Wq  = (const float*)d_in[2];
  const float* bq  = (const float*)d_in[3];
  const float* Wk  = (const float*)d_in[4];
  const float* bk  = (const float*)d_in[5];
  const float* Wv  = (const float*)d_in[6];
  const float* bv  = (const float*)d_in[7];
  const float* Wo  = (const float*)d_in[8];
  const float* bo  = (const float*)d_in[9];
  const float* lq1 = (const float*)d_in[10];
  const float* lk1 = (const float*)d_in[11];
  const float* lq2 = (const float*)d_in[12];
  const float* lk2 = (const float*)d_in[13];
  float* out = (float*)d_out;

  float *dq, *dk, *dv, *dctx, *dwt, *dhs;
  cudaGetSymbolAddress((void**)&dq,   g_q);
  cudaGetSymbolAddress((void**)&dk,   g_k);
  cudaGetSymbolAddress((void**)&dv,   g_v);
  cudaGetSymbolAddress((void**)&dctx, g_ctx);
  cudaGetSymbolAddress((void**)&dwt,  g_wt);
  cudaGetSymbolAddress((void**)&dhs,  g_hs);

  float* wtq = dwt;                              // [2048,1024]
  float* wtk = wtq + (size_t)2048 * 1024;        // [2048,1024]
  float* wtv = wtk + (size_t)2048 * 1024;        // [1024,1024]
  float* wto = wtv + (size_t)1024 * 1024;        // [1024,1024]

  lam_kernel<<<1, 32>>>(lq1, lk1, lq2, lk2);

  const int n4 = M_ * D_ / 4;
  round_copy<<<(n4 + 255) / 256, 256>>>(hs, dhs, n4);

  dim3 tthr(32, 8);
  transpose_k<<<dim3(2 * D_ / 32, D_ / 32), tthr>>>(Wq, wtq, D_, 2 * D_);
  transpose_k<<<dim3(2 * D_ / 32, D_ / 32), tthr>>>(Wk, wtk, D_, 2 * D_);
  transpose_k<<<dim3(D_ / 32, D_ / 32),     tthr>>>(Wv, wtv, D_, D_);
  transpose_k<<<dim3(D_ / 32, D_ / 32),     tthr>>>(Wo, wto, D_, D_);

  cudaFuncSetAttribute(gemm_mma, cudaFuncAttributeMaxDynamicSharedMemorySize, GSMEM_SZ);
  gemm_mma<<<dim3(2 * D_ / 128, M_ / 128), 128, GSMEM_SZ>>>(dhs, wtq, bq, dq, M_, 2 * D_, D_);
  gemm_mma<<<dim3(2 * D_ / 128, M_ / 128), 128, GSMEM_SZ>>>(dhs, wtk, bk, dk, M_, 2 * D_, D_);
  gemm_mma<<<dim3(D_ / 128, M_ / 128),     128, GSMEM_SZ>>>(dhs, wtv, bv, dv, M_, D_, D_);

  size_t smem = (size_t)(5 * 64 * 65 + 64) * sizeof(float);
  cudaFuncSetAttribute(attn_kernel, cudaFuncAttributeMaxDynamicSharedMemorySize, (int)smem);
  attn_kernel<<<dim3(S_ / 64, NH_, B_), 256, smem>>>(msk);

  gemm_mma<<<dim3(D_ / 128, M_ / 128), 128, GSMEM_SZ>>>(dctx, wto, bo, out, M_, D_, D_);
}